// round 15
// baseline (speedup 1.0000x reference)
#include <cuda_runtime.h>
#include <cstdint>

#define NN 100000
#define EE 1600000
#define NTILES 12500
#define LK 72      // stride (u32 pairs) for As and W images: per-16-lane-phase banks 8g+2t distinct -> conflict-free v2 frags
#define NLKA 212   // node As stride (u32/tf32)
#define NLKB 136   // node Bs stride

// ---------------- global scratch ----------------
__device__ float    g_aggr[(size_t)NN * 128];
__device__ uint32_t g_wimg[4 * 9216];   // bf16x2 images: Wm1|Wm2|Wc1|Wv1, layout [col][slot], stride LK

// ---------------- helpers ----------------
__device__ __forceinline__ float silu_t(float v) {          // 1-MUFU tanh silu (validated R13/R14)
    float t; asm("tanh.approx.f32 %0, %1;" : "=f"(t) : "f"(v * 0.5f));
    return fmaf(v * 0.5f, t, v * 0.5f);
}
__device__ __forceinline__ uint32_t pkbf2(float lo, float hi) {
    uint32_t r; asm("cvt.rn.bf16x2.f32 %0, %1, %2;" : "=r"(r) : "f"(hi), "f"(lo)); return r;
}
__device__ __forceinline__ uint32_t rna_tf32(float f) {
    uint32_t u; asm("cvt.rna.tf32.f32 %0, %1;" : "=r"(u) : "f"(f)); return u;
}
__device__ __forceinline__ void mma16(float c[4], const uint32_t a[4], uint32_t b0, uint32_t b1) {
    asm volatile("mma.sync.aligned.m16n8k16.row.col.f32.bf16.bf16.f32 "
                 "{%0,%1,%2,%3}, {%4,%5,%6,%7}, {%8,%9}, {%0,%1,%2,%3};"
                 : "+f"(c[0]), "+f"(c[1]), "+f"(c[2]), "+f"(c[3])
                 : "r"(a[0]), "r"(a[1]), "r"(a[2]), "r"(a[3]), "r"(b0), "r"(b1));
}
__device__ __forceinline__ void mma8(float c[4], const uint32_t a[4], uint32_t b0, uint32_t b1) {
    asm volatile("mma.sync.aligned.m16n8k8.row.col.f32.tf32.tf32.f32 "
                 "{%0,%1,%2,%3}, {%4,%5,%6,%7}, {%8,%9}, {%0,%1,%2,%3};"
                 : "+f"(c[0]), "+f"(c[1]), "+f"(c[2]), "+f"(c[3])
                 : "r"(a[0]), "r"(a[1]), "r"(a[2]), "r"(a[3]), "r"(b0), "r"(b1));
}
__device__ __forceinline__ uint32_t smem_u32(const void* p) {
    uint32_t a;
    asm("{ .reg .u64 t; cvta.to.shared.u64 t, %1; cvt.u32.u64 %0, t; }" : "=r"(a) : "l"(p));
    return a;
}
__device__ __forceinline__ void cp16(uint32_t saddr, const void* g) {
    asm volatile("cp.async.cg.shared.global [%0], [%1], 16;" :: "r"(saddr), "l"(g) : "memory");
}
#define CP_COMMIT() asm volatile("cp.async.commit_group;" ::: "memory")
#define CP_WAIT0()  asm volatile("cp.async.wait_group 0;" ::: "memory")
#define UBAR(id)    asm volatile("bar.sync %0, 256;" :: "r"(id) : "memory")

// k-pair interleave within full groups of 8 (LK=72 -> 9 full groups, no tail hazard)
__device__ __forceinline__ int physp(int p) {
    return (p & ~7) | ((p & 3) << 1) | ((p >> 2) & 1);
}

// ---------------- prep: bf16x2 interleaved-transposed weight images (stride 72) ----------------
__global__ void prep_kernel(const float* __restrict__ Wm1, const float* __restrict__ Wm2,
                            const float* __restrict__ Wc1, const float* __restrict__ Wv1) {
    int idx = blockIdx.x * blockDim.x + threadIdx.x;
    if (idx >= 4 * 9216) return;
    int img = idx / 9216;
    int r = idx - img * 9216;
    int n = r / LK;           // output col 0..127
    int kr = r - n * LK;      // logical k-pair 0..71 (all groups full)
    const float* W = (img == 0) ? Wm1 : (img == 1) ? Wm2 : (img == 2) ? Wc1 : Wv1;
    int realK = (img == 0) ? 138 : 128;
    float lo = (2 * kr < realK) ? W[(2 * kr) * 128 + n] : 0.f;
    float hi = (2 * kr + 1 < realK) ? W[(2 * kr + 1) * 128 + n] : 0.f;
    g_wimg[img * 9216 + n * LK + physp(kr)] = pkbf2(lo, hi);
}

// ---------------- init ----------------
__global__ void init_kernel(const float* __restrict__ x, const float* __restrict__ v,
                            float* __restrict__ out) {
    int idx = blockIdx.x * blockDim.x + threadIdx.x;
    int stride = gridDim.x * blockDim.x;
    for (int k = idx; k < NN * 128; k += stride) g_aggr[k] = 0.f;
    for (int k = idx; k < NN * 3; k += stride) {
        out[(size_t)NN * 64 + k] = x[k];
        out[(size_t)NN * 64 + (size_t)NN * 3 + k] = v[k];
    }
}

// ---------------- edge kernel pieces ----------------

__device__ __forceinline__ void warp_gemm(const uint32_t* __restrict__ As2,
                                          const uint32_t* __restrict__ BsT,
                                          const float* __restrict__ bias,
                                          int KB, int rw0, int cn0, int g, int t,
                                          float c[2][8][4]) {
#pragma unroll
    for (int nt = 0; nt < 8; nt++) {
        float b0v = bias[cn0 + nt * 8 + 2 * t];
        float b1v = bias[cn0 + nt * 8 + 2 * t + 1];
        c[0][nt][0] = b0v; c[0][nt][1] = b1v; c[0][nt][2] = b0v; c[0][nt][3] = b1v;
        c[1][nt][0] = b0v; c[1][nt][1] = b1v; c[1][nt][2] = b0v; c[1][nt][3] = b1v;
    }
    const uint32_t* arow = As2 + (rw0 + g) * LK + 2 * t;
    const uint32_t* brow = BsT + (cn0 + g) * LK + 2 * t;
#pragma unroll 1
    for (int kb = 0; kb < KB; kb++) {
        uint2 a00 = *(const uint2*)(arow + kb * 8);
        uint2 a01 = *(const uint2*)(arow + 8 * LK + kb * 8);
        uint2 a10 = *(const uint2*)(arow + 16 * LK + kb * 8);
        uint2 a11 = *(const uint2*)(arow + 24 * LK + kb * 8);
        uint32_t a0[4] = {a00.x, a01.x, a00.y, a01.y};
        uint32_t a1[4] = {a10.x, a11.x, a10.y, a11.y};
#pragma unroll
        for (int nt = 0; nt < 8; nt++) {
            uint2 b = *(const uint2*)(brow + (nt * 8) * LK + kb * 8);
            mma16(c[0][nt], a0, b.x, b.y);
            mma16(c[1][nt], a1, b.x, b.y);
        }
    }
}

__device__ __forceinline__ void store_act(uint32_t* __restrict__ As2, float c[2][8][4],
                                          const int* __restrict__ srow, bool do_red,
                                          int rw0, int cn0, int g, int t) {
#pragma unroll
    for (int mh = 0; mh < 2; mh++) {
        int r0 = rw0 + mh * 16 + g;
#pragma unroll
        for (int nt = 0; nt < 8; nt++) {
            int slot = (cn0 >> 1) + ((nt >> 1) << 3) + (t << 1) + (nt & 1);
            float v0 = silu_t(c[mh][nt][0]);
            float v1 = silu_t(c[mh][nt][1]);
            float v2 = silu_t(c[mh][nt][2]);
            float v3 = silu_t(c[mh][nt][3]);
            As2[r0 * LK + slot] = pkbf2(v0, v1);
            As2[(r0 + 8) * LK + slot] = pkbf2(v2, v3);
            if (do_red) {
                int col = cn0 + nt * 8 + 2 * t;
                float* d0 = g_aggr + (size_t)srow[r0] * 128 + col;
                float* d1 = g_aggr + (size_t)srow[r0 + 8] * 128 + col;
                asm volatile("red.global.add.v2.f32 [%0], {%1,%2};" :: "l"(d0), "f"(v0), "f"(v1) : "memory");
                asm volatile("red.global.add.v2.f32 [%0], {%1,%2};" :: "l"(d1), "f"(v2), "f"(v3) : "memory");
            }
        }
    }
}

__device__ __forceinline__ void reduce_rows(float c[2][8][4], const float* __restrict__ w2,
                                            float* __restrict__ sredh,
                                            int rw0, int cn0, int g, int t) {
#pragma unroll
    for (int mh = 0; mh < 2; mh++) {
        float s0 = 0.f, s1 = 0.f;
#pragma unroll
        for (int nt = 0; nt < 8; nt++) {
            int col = cn0 + nt * 8 + 2 * t;
            float w0 = w2[col], w1 = w2[col + 1];
            s0 += silu_t(c[mh][nt][0]) * w0 + silu_t(c[mh][nt][1]) * w1;
            s1 += silu_t(c[mh][nt][2]) * w0 + silu_t(c[mh][nt][3]) * w1;
        }
        s0 += __shfl_xor_sync(0xffffffffu, s0, 1);
        s0 += __shfl_xor_sync(0xffffffffu, s0, 2);
        s1 += __shfl_xor_sync(0xffffffffu, s1, 1);
        s1 += __shfl_xor_sync(0xffffffffu, s1, 2);
        if (t == 0) {
            sredh[rw0 + mh * 16 + g] = s0;
            sredh[rw0 + mh * 16 + g + 8] = s1;
        }
    }
}

// SMEM (u32): W images 4*9216=36864 | As2 unit0 9216 | As2 unit1 9216 |
//             per-unit misc (ssq128, srel384, sredp128, sredq128, srow128)=896 x2 | sbias 768
#define EDGE_SMEM_U32  (36864 + 2 * 9216 + 2 * 896 + 768)   // 57856
#define EDGE_SMEM_BYTES (EDGE_SMEM_U32 * 4)                 // 231424 <= 232448 (227KB max)

__global__ void __launch_bounds__(512, 1)
edge_mma_kernel(const float* __restrict__ h, const float* __restrict__ x,
                const int* __restrict__ ei, const float* __restrict__ ea,
                const float* __restrict__ bm1, const float* __restrict__ bm2,
                const float* __restrict__ bc1, const float* __restrict__ bc2,
                const float* __restrict__ bv1, const float* __restrict__ bv2,
                const float* __restrict__ Wc2, const float* __restrict__ Wv2,
                float* __restrict__ outx, float* __restrict__ outv) {
    extern __shared__ uint32_t smu[];
    uint32_t* Wimg  = smu;                         // 36864: 4 images, stride LK
    const int tid = threadIdx.x;
    const int unit = tid >> 8;                     // 0 or 1
    const int utid = tid & 255;
    uint32_t* As2  = smu + 36864 + unit * 9216;    // per-unit A tile
    float* ssq     = (float*)(smu + 36864 + 2 * 9216) + unit * 896;   // 128
    float* srel    = ssq + 128;                    // 384
    float* sredp   = srel + 384;                   // 128
    float* sredq   = sredp + 128;                  // 128
    int*   srow    = (int*)(sredq + 128);          // 128
    float* sbias   = (float*)(smu + 36864 + 2 * 9216 + 2 * 896);      // 768 shared

    const int w = utid >> 5, lane = utid & 31;
    const int g = lane >> 2, t = lane & 3;
    const int rw0 = (w & 3) * 32, cn0 = (w >> 2) * 64;
    const int barid = 1 + unit;

    // ---- one-time: load all 4 weight images + biases ----
    {
        uint32_t wAddr = smem_u32(Wimg);
        for (int i = tid; i < 9216; i += 512)
            cp16(wAddr + (uint32_t)i * 16u, (const char*)g_wimg + (size_t)i * 16);
        CP_COMMIT();
        for (int i = tid; i < 768; i += 512) {
            int j = i & 127, gg = i >> 7;
            sbias[i] = (gg == 0) ? bm1[j] : (gg == 1) ? bm2[j] : (gg == 2) ? bc1[j] :
                       (gg == 3) ? bv1[j] : (gg == 4) ? Wc2[j] : Wv2[j];
        }
        CP_WAIT0();
        __syncthreads();   // only full-CTA barrier; units independent after this
    }
    const uint32_t* W0 = Wimg;               // Wm1
    const uint32_t* W1 = Wimg + 9216;        // Wm2
    const uint32_t* W2 = Wimg + 2 * 9216;    // Wc1
    const uint32_t* W3 = Wimg + 3 * 9216;    // Wv1
    const float bc2v = bc2[0], bv2v = bv2[0];

    const int uid = blockIdx.x * 2 + unit;
    const int nunits = gridDim.x * 2;

    float c[2][8][4];

    for (int tile = uid; tile < NTILES; tile += nunits) {
        const int e0 = tile * 128;

        // ---- phase 0: metadata (utid<128) ----
        if (utid < 128) {
            int e = e0 + utid;
            int r = ei[e], cc = ei[EE + e];
            srow[utid] = r;
            float dx = x[r * 3 + 0] - x[cc * 3 + 0];
            float dy = x[r * 3 + 1] - x[cc * 3 + 1];
            float dz = x[r * 3 + 2] - x[cc * 3 + 2];
            float sq = dx * dx + dy * dy + dz * dz;
            ssq[utid] = sq;
            srel[utid * 3 + 0] = dx; srel[utid * 3 + 1] = dy; srel[utid * 3 + 2] = dz;
            float4 ea0 = ((const float4*)(ea + (size_t)e * 8))[0];
            float4 ea1 = ((const float4*)(ea + (size_t)e * 8))[1];
            uint32_t* dst = As2 + utid * LK + 64;
            dst[0] = pkbf2(sq, dz);
            dst[2] = pkbf2(ea0.x, ea0.y);
            dst[4] = pkbf2(ea0.z, ea0.w);
            dst[6] = pkbf2(ea1.x, ea1.y);
            dst[1] = pkbf2(ea1.z, ea1.w);
            dst[3] = 0u; dst[5] = 0u; dst[7] = 0u;
        }
        // ---- gather h rows (all 256 unit threads; reads ei directly) ----
        {
            int r = utid >> 1, part = utid & 1;
            int node = ei[(part ? EE : 0) + e0 + r];
            const float4* hp = (const float4*)(h + (size_t)node * 64);
            uint32_t* dst = As2 + r * LK;
            int pb = part * 32;
#pragma unroll
            for (int q = 0; q < 16; q++) {
                float4 f = hp[q];
                dst[physp(pb + q * 2)]     = pkbf2(f.x, f.y);
                dst[physp(pb + q * 2 + 1)] = pkbf2(f.z, f.w);
            }
        }
        UBAR(barid);                                   // 1: gather done

        warp_gemm(As2, W0, sbias + 0, 9, rw0, cn0, g, t, c);     // G1
        UBAR(barid);                                   // 2: G1 reads done
        store_act(As2, c, srow, false, rw0, cn0, g, t);          // ep1
        UBAR(barid);                                   // 3: H1 written

        warp_gemm(As2, W1, sbias + 128, 8, rw0, cn0, g, t, c);   // G2
        UBAR(barid);                                   // 4: G2 reads done
        store_act(As2, c, srow, true, rw0, cn0, g, t);           // ep2: msg + aggr
        UBAR(barid);                                   // 5: msg written

        warp_gemm(As2, W2, sbias + 256, 8, rw0, cn0, g, t, c);   // G3
        reduce_rows(c, sbias + 512, (w >> 2) ? sredq : sredp, rw0, cn0, g, t);
        UBAR(barid);                                   // 6: sred(3) ready

        warp_gemm(As2, W3, sbias + 384, 8, rw0, cn0, g, t, c);   // G4 (As stable, W3 static)
        if (utid < 128) {                              // scatter3 hides under G4 tail
            float tot = sredp[utid] + sredq[utid] + bc2v;
            float wv = __fdividef(tot, ssq[utid] + 1e-8f);
            int rw = srow[utid];
            atomicAdd(outx + (size_t)rw * 3 + 0, srel[utid * 3 + 0] * wv);
            atomicAdd(outx + (size_t)rw * 3 + 1, srel[utid * 3 + 1] * wv);
            atomicAdd(outx + (size_t)rw * 3 + 2, srel[utid * 3 + 2] * wv);
        }
        UBAR(barid);                                   // 7: scatter3 reads done
        reduce_rows(c, sbias + 640, (w >> 2) ? sredq : sredp, rw0, cn0, g, t);
        UBAR(barid);                                   // 8: sred(4) ready
        if (utid < 128) {
            float tot = sredp[utid] + sredq[utid] + bv2v;
            float wv = __fdividef(tot, ssq[utid] + 1e-8f);
            int rw = srow[utid];
            atomicAdd(outv + (size_t)rw * 3 + 0, srel[utid * 3 + 0] * wv);
            atomicAdd(outv + (size_t)rw * 3 + 1, srel[utid * 3 + 1] * wv);
            atomicAdd(outv + (size_t)rw * 3 + 2, srel[utid * 3 + 2] * wv);
        }
        UBAR(barid);                                   // 9: tile done (guards next gather)
    }
}

// ---------------- node kernel: tf32 mma (R14 validated) ----------------
#define NODE_SMEM_U32  (27136 + 26112)
#define NODE_SMEM_BYTES (NODE_SMEM_U32 * 4)

__global__ void __launch_bounds__(256, 1)
node_mma_kernel(const float* __restrict__ h,
                const float* __restrict__ Wn1, const float* __restrict__ bn1,
                const float* __restrict__ Wn2, const float* __restrict__ bn2,
                float* __restrict__ out) {
    extern __shared__ uint32_t smu[];
    uint32_t* As32 = smu;
    uint32_t* Bs32 = As32 + 27136;

    const int tid = threadIdx.x;
    const int w = tid >> 5, lane = tid & 31;
    const int g = lane >> 2, t = lane & 3;
    const int rw0 = (w & 3) * 32, cn0 = (w >> 2) * 64;
    const int n0 = blockIdx.x * 128;

    {
        int r = tid >> 1, part = tid & 1;
        int n = n0 + r;
        int nc = (n < NN) ? n : (NN - 1);
        uint32_t* dst = As32 + r * NLKA;
        if (part == 0) {
            const float4* hp = (const float4*)(h + (size_t)nc * 64);
#pragma unroll
            for (int q = 0; q < 16; q++) {
                float4 f = hp[q];
                dst[q * 4 + 0] = rna_tf32(f.x); dst[q * 4 + 1] = rna_tf32(f.y);
                dst[q * 4 + 2] = rna_tf32(f.z); dst[q * 4 + 3] = rna_tf32(f.w);
            }
            const float4* ap = (const float4*)(g_aggr + (size_t)nc * 128);
#pragma unroll
            for (int q = 0; q < 8; q++) {
                float4 f = ap[q];
                dst[64 + q * 4 + 0] = rna_tf32(f.x); dst[64 + q * 4 + 1] = rna_tf32(f.y);
                dst[64 + q * 4 + 2] = rna_tf32(f.z); dst[64 + q * 4 + 3] = rna_tf32(f.w);
            }
        } else {
            const float4* ap = (const float4*)(g_aggr + (size_t)nc * 128 + 32);
#pragma unroll
            for (int q = 0; q < 24; q++) {
                float4 f = ap[q];
                dst[96 + q * 4 + 0] = rna_tf32(f.x); dst[96 + q * 4 + 1] = rna_tf32(f.y);
                dst[96 + q * 4 + 2] = rna_tf32(f.z); dst[96 + q * 4 + 3] = rna_tf32(f.w);
            }
        }
    }
    for (int idx = tid; idx < 192 * 32; idx += 256) {
        int k = idx >> 5, j = idx & 31;
        float4 f = ((const float4*)Wn1)[k * 32 + j];
        uint32_t* d = Bs32 + k * NLKB + j * 4;
        d[0] = rna_tf32(f.x); d[1] = rna_tf32(f.y); d[2] = rna_tf32(f.z); d[3] = rna_tf32(f.w);
    }
    __syncthreads();

    float c[2][8][4];
#pragma unroll
    for (int nt = 0; nt < 8; nt++) {
        float b0v = bn1[cn0 + nt * 8 + 2 * t];
        float b1v = bn1[cn0 + nt * 8 + 2 * t + 1];
        c[0][nt][0] = b0v; c[0][nt][1] = b1v; c[0][nt][2] = b0v; c[0][nt][3] = b1v;
        c[1][nt][0] = b0v; c[1][nt][1] = b1v; c[1][nt][2] = b0v; c[1][nt][3] = b1v;
    }
    {
        const uint32_t* ar0 = As32 + (rw0 + g) * NLKA + t;
        const uint32_t* ar1 = As32 + (rw0 + 16 + g) * NLKA + t;
        const uint32_t* br  = Bs32 + t * NLKB + cn0 + g;
#pragma unroll 1
        for (int kb = 0; kb < 24; kb++) {
            uint32_t a0[4], a1[4];
            a0[0] = ar0[kb * 8];       a0[1] = ar0[8 * NLKA + kb * 8];
            a0[2] = ar0[kb * 8 + 4];   a0[3] = ar0[8 * NLKA + kb * 8 + 4];
            a1[0] = ar1[kb * 8];       a1[1] = ar1[8 * NLKA + kb * 8];
            a1[2] = ar1[kb * 8 + 4];   a1[3] = ar1[8 * NLKA + kb * 8 + 4];
#pragma unroll
            for (int nt = 0; nt < 8; nt++) {
                uint32_t b0 = br[(kb * 8) * NLKB + nt * 8];
                uint32_t b1 = br[(kb * 8 + 4) * NLKB + nt * 8];
                mma8(c[0][nt], a0, b0, b1);
                mma8(c[1][nt], a1, b0, b1);
            }
        }
    }
    __syncthreads();
#pragma unroll
    for (int mh = 0; mh < 2; mh++) {
        int r0 = rw0 + mh * 16 + g;
#pragma unroll
        for (int nt = 0; nt < 8; nt++) {
            int col = cn0 + nt * 8 + 2 * t;
            As32[r0 * NLKA + col]           = rna_tf32(silu_t(c[mh][nt][0]));
            As32[r0 * NLKA + col + 1]       = rna_tf32(silu_t(c[mh][nt][1]));
            As32[(r0 + 8) * NLKA + col]     = rna_tf32(silu_t(c[mh][nt][2]));
            As32[(r0 + 8) * NLKA + col + 1] = rna_tf32(silu_t(c[mh][nt][3]));
        }
    }
    for (int idx = tid; idx < 128 * 16; idx += 256) {
        int k = idx >> 4, j = idx & 15;
        float4 f = ((const float4*)Wn2)[k * 16 + j];
        uint32_t* d = Bs32 + k * NLKB + j * 4;
        d[0] = rna_tf32(f.x); d[1] = rna_tf32(f.y); d[2] = rna_tf32(f.z); d[3] = rna_tf32(f.w);
    }
    __syncthreads();

    {
        const int rz = w * 16;
        float c2[8][4];
#pragma unroll
        for (int nt = 0; nt < 8; nt++) {
            float b0v = bn2[nt * 8 + 2 * t];
            float b1v = bn2[nt * 8 + 2 * t + 1];
            c2[nt][0] = b0v; c2[nt][1] = b1v; c2[nt][2] = b0v; c2[nt][3] = b1v;
        }
        const uint32_t* ar = As32 + (rz + g) * NLKA + t;
        const uint32_t* br = Bs32 + t * NLKB + g;
#pragma unroll 1
        for (int kb = 0; kb < 16; kb++) {
            uint32_t a0[4];
            a0[0] = ar[kb * 8];       a0[1] = ar[8 * NLKA + kb * 8];
            a0[2] = ar[kb * 8 + 4];   a0[3] = ar[8 * NLKA + kb * 8 + 4];
#pragma unroll
            for (int nt = 0; nt < 8; nt++) {
                uint32_t b0 = br[(kb * 8) * NLKB + nt * 8];
                uint32_t b1 = br[(kb * 8 + 4) * NLKB + nt * 8];
                mma8(c2[nt], a0, b0, b1);
            }
        }
        int nA = n0 + rz + g, nB = nA + 8;
#pragma unroll
        for (int nt = 0; nt < 8; nt++) {
            int col = nt * 8 + 2 * t;
            if (nA < NN) {
                float2 hv = *(const float2*)(h + (size_t)nA * 64 + col);
                float2 o; o.x = hv.x + c2[nt][0]; o.y = hv.y + c2[nt][1];
                *(float2*)(out + (size_t)nA * 64 + col) = o;
            }
            if (nB < NN) {
                float2 hv = *(const float2*)(h + (size_t)nB * 64 + col);
                float2 o; o.x = hv.x + c2[nt][2]; o.y = hv.y + c2[nt][3];
                *(float2*)(out + (size_t)nB * 64 + col) = o;
            }
        }
    }
}

// ---------------- launch ----------------
extern "C" void kernel_launch(void* const* d_in, const int* in_sizes, int n_in,
                              void* d_out, int out_size) {
    const float* h   = (const float*)d_in[0];
    const float* x   = (const float*)d_in[1];
    const float* v   = (const float*)d_in[2];
    const int*   ei  = (const int*)d_in[3];
    const float* ea  = (const float*)d_in[4];
    const float* Wm1 = (const float*)d_in[5];
    const float* bm1 = (const float*)d_in[6];
    const float* Wm2 = (const float*)d_in[7];
    const float* bm2 = (const float*)d_in[8];
    const float* Wn1 = (const float*)d_in[9];
    const float* bn1 = (const float*)d_in[10];
    const float* Wn2 = (const float*)d_in[11];
    const float* bn2 = (const float*)d_in[12];
    const float* Wc1 = (const float*)d_in[13];
    const float* bc1 = (const float*)d_in[14];
    const float* Wc2 = (const float*)d_in[15];
    const float* bc2 = (const float*)d_in[16];
    const float* Wv1 = (const float*)d_in[17];
    const float* bv1 = (const float*)d_in[18];
    const float* Wv2 = (const float*)d_in[19];
    const float* bv2 = (const float*)d_in[20];
    float* out = (float*)d_out;

    cudaFuncSetAttribute(edge_mma_kernel, cudaFuncAttributeMaxDynamicSharedMemorySize, EDGE_SMEM_BYTES);
    cudaFuncSetAttribute(node_mma_kernel, cudaFuncAttributeMaxDynamicSharedMemorySize, NODE_SMEM_BYTES);

    prep_kernel<<<(4 * 9216 + 255) / 256, 256>>>(Wm1, Wm2, Wc1, Wv1);
    init_kernel<<<2048, 256>>>(x, v, out);
    edge_mma_kernel<<<148, 512, EDGE_SMEM_BYTES>>>(
        h, x, ei, ea, bm1, bm2, bc1, bc2, bv1, bv2, Wc2, Wv2,
        out + (size_t)NN * 64, out + (size_t)NN * 64 + (size_t)NN * 3);
    node_mma_kernel<<<(NN + 127) / 128, 256, NODE_SMEM_BYTES>>>(h, Wn1, bn1, Wn2, bn2, out);
}

// round 16
// speedup vs baseline: 1.1125x; 1.1125x over previous
#include <cuda_runtime.h>
#include <cstdint>

#define NN 100000
#define EE 1600000
#define LKA2 76    // As row stride (u32 pairs): 76 mod 32 = 12 -> 2-wavefront v2 frags
#define LKB2 76    // BsT row stride (u32 pairs), same property
#define NLKA 212   // node As stride (u32/tf32): conflict-free scalar frags
#define NLKB 136   // node Bs stride

// ---------------- global scratch ----------------
__device__ float    g_aggr[(size_t)NN * 128];
__device__ uint32_t g_wimg[4 * 9728];   // bf16x2 images: Wm1|Wm2|Wc1|Wv1, layout [col][slot] = smem BsT

// ---------------- helpers ----------------
__device__ __forceinline__ float silu_t(float v) {          // 1-MUFU tanh silu (R13/R14 validated)
    float t; asm("tanh.approx.f32 %0, %1;" : "=f"(t) : "f"(v * 0.5f));
    return fmaf(v * 0.5f, t, v * 0.5f);
}
// pack 2 floats -> bf16x2 (lo = first arg). PTX: first src -> HIGH half.
__device__ __forceinline__ uint32_t pkbf2(float lo, float hi) {
    uint32_t r; asm("cvt.rn.bf16x2.f32 %0, %1, %2;" : "=r"(r) : "f"(hi), "f"(lo)); return r;
}
__device__ __forceinline__ uint32_t rna_tf32(float f) {
    uint32_t u; asm("cvt.rna.tf32.f32 %0, %1;" : "=r"(u) : "f"(f)); return u;
}
__device__ __forceinline__ void mma16(float c[4], const uint32_t a[4], uint32_t b0, uint32_t b1) {
    asm volatile("mma.sync.aligned.m16n8k16.row.col.f32.bf16.bf16.f32 "
                 "{%0,%1,%2,%3}, {%4,%5,%6,%7}, {%8,%9}, {%0,%1,%2,%3};"
                 : "+f"(c[0]), "+f"(c[1]), "+f"(c[2]), "+f"(c[3])
                 : "r"(a[0]), "r"(a[1]), "r"(a[2]), "r"(a[3]), "r"(b0), "r"(b1));
}
__device__ __forceinline__ void mma8(float c[4], const uint32_t a[4], uint32_t b0, uint32_t b1) {
    asm volatile("mma.sync.aligned.m16n8k8.row.col.f32.tf32.tf32.f32 "
                 "{%0,%1,%2,%3}, {%4,%5,%6,%7}, {%8,%9}, {%0,%1,%2,%3};"
                 : "+f"(c[0]), "+f"(c[1]), "+f"(c[2]), "+f"(c[3])
                 : "r"(a[0]), "r"(a[1]), "r"(a[2]), "r"(a[3]), "r"(b0), "r"(b1));
}
__device__ __forceinline__ uint32_t smem_u32(const void* p) {
    uint32_t a;
    asm("{ .reg .u64 t; cvta.to.shared.u64 t, %1; cvt.u32.u64 %0, t; }" : "=r"(a) : "l"(p));
    return a;
}
__device__ __forceinline__ void cp16(uint32_t saddr, const void* g) {
    asm volatile("cp.async.cg.shared.global [%0], [%1], 16;" :: "r"(saddr), "l"(g) : "memory");
}
#define CP_COMMIT() asm volatile("cp.async.commit_group;" ::: "memory")
#define CP_WAIT0()  asm volatile("cp.async.wait_group 0;" ::: "memory")

// k-pair interleave: logical pair p -> physical slot. Valid only for p < 72 (full groups of 8).
__device__ __forceinline__ int physp(int p) {
    return (p & ~7) | ((p & 3) << 1) | ((p >> 2) & 1);
}

// ---------------- setup: weight images + aggr zero + x/v seeds (fused) ----------------
__global__ void setup_kernel(const float* __restrict__ x, const float* __restrict__ v,
                             float* __restrict__ out,
                             const float* __restrict__ Wm1, const float* __restrict__ Wm2,
                             const float* __restrict__ Wc1, const float* __restrict__ Wv1) {
    int idx = blockIdx.x * blockDim.x + threadIdx.x;
    int stride = gridDim.x * blockDim.x;
    for (int k = idx; k < 4 * 9728; k += stride) {
        int img = k / 9728;
        int r = k - img * 9728;
        int n = r / 76;
        int kr = r - n * 76;
        if (kr >= 72) continue;   // tail group would alias next column (R11 bug fix)
        const float* W = (img == 0) ? Wm1 : (img == 1) ? Wm2 : (img == 2) ? Wc1 : Wv1;
        int realK = (img == 0) ? 138 : 128;
        float lo = (2 * kr < realK) ? W[(2 * kr) * 128 + n] : 0.f;
        float hi = (2 * kr + 1 < realK) ? W[(2 * kr + 1) * 128 + n] : 0.f;
        g_wimg[img * 9728 + n * 76 + physp(kr)] = pkbf2(lo, hi);
    }
    for (int k = idx; k < NN * 128; k += stride) g_aggr[k] = 0.f;
    for (int k = idx; k < NN * 3; k += stride) {
        out[(size_t)NN * 64 + k] = x[k];
        out[(size_t)NN * 64 + (size_t)NN * 3 + k] = v[k];
    }
}

// ---------------- edge kernel pieces ----------------

__device__ __forceinline__ void load_B_async(uint32_t bsAddr, const uint32_t* __restrict__ gsrc, int tid) {
    for (int i = tid; i < 2432; i += 256)
        cp16(bsAddr + (uint32_t)i * 16u, (const char*)gsrc + (size_t)i * 16);
    CP_COMMIT();
}

__device__ __forceinline__ void warp_gemm(const uint32_t* __restrict__ As2,
                                          const uint32_t* __restrict__ BsT,
                                          const float* __restrict__ bias,
                                          int KB, int rw0, int cn0, int g, int t,
                                          float c[2][8][4]) {
#pragma unroll
    for (int nt = 0; nt < 8; nt++) {
        float b0v = bias[cn0 + nt * 8 + 2 * t];
        float b1v = bias[cn0 + nt * 8 + 2 * t + 1];
        c[0][nt][0] = b0v; c[0][nt][1] = b1v; c[0][nt][2] = b0v; c[0][nt][3] = b1v;
        c[1][nt][0] = b0v; c[1][nt][1] = b1v; c[1][nt][2] = b0v; c[1][nt][3] = b1v;
    }
    const uint32_t* arow = As2 + (rw0 + g) * LKA2 + 2 * t;
    const uint32_t* brow = BsT + (cn0 + g) * LKB2 + 2 * t;
#pragma unroll 1
    for (int kb = 0; kb < KB; kb++) {
        uint2 a00 = *(const uint2*)(arow + kb * 8);
        uint2 a01 = *(const uint2*)(arow + 8 * LKA2 + kb * 8);
        uint2 a10 = *(const uint2*)(arow + 16 * LKA2 + kb * 8);
        uint2 a11 = *(const uint2*)(arow + 24 * LKA2 + kb * 8);
        uint32_t a0[4] = {a00.x, a01.x, a00.y, a01.y};
        uint32_t a1[4] = {a10.x, a11.x, a10.y, a11.y};
#pragma unroll
        for (int nt = 0; nt < 8; nt++) {
            uint2 b = *(const uint2*)(brow + (nt * 8) * LKB2 + kb * 8);
            mma16(c[0][nt], a0, b.x, b.y);
            mma16(c[1][nt], a1, b.x, b.y);
        }
    }
}

__device__ __forceinline__ void store_act(uint32_t* __restrict__ As2, float c[2][8][4],
                                          const int* __restrict__ srow, bool do_red,
                                          int rw0, int cn0, int g, int t) {
#pragma unroll
    for (int mh = 0; mh < 2; mh++) {
        int r0 = rw0 + mh * 16 + g;
#pragma unroll
        for (int nt = 0; nt < 8; nt++) {
            int slot = (cn0 >> 1) + ((nt >> 1) << 3) + (t << 1) + (nt & 1);
            float v0 = silu_t(c[mh][nt][0]);
            float v1 = silu_t(c[mh][nt][1]);
            float v2 = silu_t(c[mh][nt][2]);
            float v3 = silu_t(c[mh][nt][3]);
            As2[r0 * LKA2 + slot] = pkbf2(v0, v1);
            As2[(r0 + 8) * LKA2 + slot] = pkbf2(v2, v3);
            if (do_red) {
                int col = cn0 + nt * 8 + 2 * t;
                float* d0 = g_aggr + (size_t)srow[r0] * 128 + col;
                float* d1 = g_aggr + (size_t)srow[r0 + 8] * 128 + col;
                asm volatile("red.global.add.v2.f32 [%0], {%1,%2};" :: "l"(d0), "f"(v0), "f"(v1) : "memory");
                asm volatile("red.global.add.v2.f32 [%0], {%1,%2};" :: "l"(d1), "f"(v2), "f"(v3) : "memory");
            }
        }
    }
}

__device__ __forceinline__ void reduce_rows(float c[2][8][4], const float* __restrict__ w2,
                                            float* __restrict__ sredh,
                                            int rw0, int cn0, int g, int t) {
#pragma unroll
    for (int mh = 0; mh < 2; mh++) {
        float s0 = 0.f, s1 = 0.f;
#pragma unroll
        for (int nt = 0; nt < 8; nt++) {
            int col = cn0 + nt * 8 + 2 * t;
            float w0 = w2[col], w1 = w2[col + 1];
            s0 += silu_t(c[mh][nt][0]) * w0 + silu_t(c[mh][nt][1]) * w1;
            s1 += silu_t(c[mh][nt][2]) * w0 + silu_t(c[mh][nt][3]) * w1;
        }
        s0 += __shfl_xor_sync(0xffffffffu, s0, 1);
        s0 += __shfl_xor_sync(0xffffffffu, s0, 2);
        s1 += __shfl_xor_sync(0xffffffffu, s1, 1);
        s1 += __shfl_xor_sync(0xffffffffu, s1, 2);
        if (t == 0) {
            sredh[rw0 + mh * 16 + g] = s0;
            sredh[rw0 + mh * 16 + g + 8] = s1;
        }
    }
}

// SMEM (u32): As2 9728 | BsT 9728 | sbias 768 | ssq 128 | srel 384 | sredp 128 | sredq 128 | srow 128 | scol 128
#define EDGE_SMEM_U32  (9728 + 9728 + 768 + 128 + 384 + 128 + 128 + 128 + 128)
#define EDGE_SMEM_BYTES (EDGE_SMEM_U32 * 4)   // 84992 -> 2 CTAs/SM, ~58KB L1 preserved

__global__ void __launch_bounds__(256, 2)
edge_mma_kernel(const float* __restrict__ h, const float* __restrict__ x,
                const int* __restrict__ ei, const float* __restrict__ ea,
                const float* __restrict__ bm1, const float* __restrict__ bm2,
                const float* __restrict__ bc1, const float* __restrict__ bc2,
                const float* __restrict__ bv1, const float* __restrict__ bv2,
                const float* __restrict__ Wc2, const float* __restrict__ Wv2,
                float* __restrict__ outx, float* __restrict__ outv) {
    extern __shared__ uint32_t smu[];
    uint32_t* As2  = smu;
    uint32_t* BsT  = As2 + 9728;
    float* sbias   = (float*)(BsT + 9728);
    float* ssq     = sbias + 768;
    float* srel    = ssq + 128;
    float* sredp   = srel + 384;
    float* sredq   = sredp + 128;
    int*   srow    = (int*)(sredq + 128);
    int*   scol    = srow + 128;

    const int tid = threadIdx.x;
    const int w = tid >> 5, lane = tid & 31;
    const int g = lane >> 2, t = lane & 3;
    const int rw0 = (w & 3) * 32, cn0 = (w >> 2) * 64;
    const int e0 = blockIdx.x * 128;
    const uint32_t bsAddr = smem_u32(BsT);

    load_B_async(bsAddr, g_wimg + 0, tid);

    if (tid < 128) {
        int e = e0 + tid;
        int r = ei[e], cc = ei[EE + e];
        srow[tid] = r; scol[tid] = cc;
        float dx = x[r * 3 + 0] - x[cc * 3 + 0];
        float dy = x[r * 3 + 1] - x[cc * 3 + 1];
        float dz = x[r * 3 + 2] - x[cc * 3 + 2];
        float sq = dx * dx + dy * dy + dz * dz;
        ssq[tid] = sq;
        srel[tid * 3 + 0] = dx; srel[tid * 3 + 1] = dy; srel[tid * 3 + 2] = dz;
        float4 ea0 = ((const float4*)(ea + (size_t)e * 8))[0];
        float4 ea1 = ((const float4*)(ea + (size_t)e * 8))[1];
        uint32_t* dst = As2 + tid * LKA2 + 64;
        dst[0] = pkbf2(sq, dz);
        dst[2] = pkbf2(ea0.x, ea0.y);
        dst[4] = pkbf2(ea0.z, ea0.w);
        dst[6] = pkbf2(ea1.x, ea1.y);
        dst[1] = pkbf2(ea1.z, ea1.w);
        dst[3] = 0u; dst[5] = 0u; dst[7] = 0u;
    } else {
        for (int i = tid - 128; i < 768; i += 128) {
            int j = i & 127, gg = i >> 7;
            sbias[i] = (gg == 0) ? bm1[j] : (gg == 1) ? bm2[j] : (gg == 2) ? bc1[j] :
                       (gg == 3) ? bv1[j] : (gg == 4) ? Wc2[j] : Wv2[j];
        }
    }
    __syncthreads();

    {
        int r = tid >> 1, part = tid & 1;
        int node = part ? scol[r] : srow[r];
        const float4* hp = (const float4*)(h + (size_t)node * 64);
        uint32_t* dst = As2 + r * LKA2;
        int pb = part * 32;
#pragma unroll
        for (int q = 0; q < 16; q++) {
            float4 f = hp[q];
            dst[physp(pb + q * 2)]     = pkbf2(f.x, f.y);
            dst[physp(pb + q * 2 + 1)] = pkbf2(f.z, f.w);
        }
    }
    CP_WAIT0();
    __syncthreads();

    float c[2][8][4];

    // GEMM1
    warp_gemm(As2, BsT, sbias + 0, 9, rw0, cn0, g, t, c);
    __syncthreads();
    load_B_async(bsAddr, g_wimg + 9728, tid);
    store_act(As2, c, srow, false, rw0, cn0, g, t);
    CP_WAIT0();
    __syncthreads();

    // GEMM2 -> msg + aggregation
    warp_gemm(As2, BsT, sbias + 128, 8, rw0, cn0, g, t, c);
    __syncthreads();
    load_B_async(bsAddr, g_wimg + 2 * 9728, tid);
    store_act(As2, c, srow, true, rw0, cn0, g, t);
    CP_WAIT0();
    __syncthreads();

    // GEMM3 -> x-weights (reduce3 is register-local: runs BEFORE the barrier;
    // then x-scatter overlaps the Wv1 cp.async wait — saves one barrier vs R14)
    warp_gemm(As2, BsT, sbias + 256, 8, rw0, cn0, g, t, c);
    reduce_rows(c, sbias + 512, (w >> 2) ? sredq : sredp, rw0, cn0, g, t);
    __syncthreads();                                  // BsT reads done + sred ready
    load_B_async(bsAddr, g_wimg + 3 * 9728, tid);
    if (tid < 128) {
        float tot = sredp[tid] + sredq[tid] + bc2[0];
        float wv = __fdividef(tot, ssq[tid] + 1e-8f);
        int rw = srow[tid];
        atomicAdd(outx + (size_t)rw * 3 + 0, srel[tid * 3 + 0] * wv);
        atomicAdd(outx + (size_t)rw * 3 + 1, srel[tid * 3 + 1] * wv);
        atomicAdd(outx + (size_t)rw * 3 + 2, srel[tid * 3 + 2] * wv);
    }
    CP_WAIT0();
    __syncthreads();

    // GEMM4 -> v-weights
    warp_gemm(As2, BsT, sbias + 384, 8, rw0, cn0, g, t, c);
    reduce_rows(c, sbias + 640, (w >> 2) ? sredq : sredp, rw0, cn0, g, t);
    __syncthreads();
    if (tid < 128) {
        float tot = sredp[tid] + sredq[tid] + bv2[0];
        float wv = __fdividef(tot, ssq[tid] + 1e-8f);
        int rw = srow[tid];
        atomicAdd(outv + (size_t)rw * 3 + 0, srel[tid * 3 + 0] * wv);
        atomicAdd(outv + (size_t)rw * 3 + 1, srel[tid * 3 + 1] * wv);
        atomicAdd(outv + (size_t)rw * 3 + 2, srel[tid * 3 + 2] * wv);
    }
}

// ---------------- node kernel: tf32 mma (R14 validated) ----------------
#define NODE_SMEM_U32  (27136 + 26112)
#define NODE_SMEM_BYTES (NODE_SMEM_U32 * 4)

__global__ void __launch_bounds__(256, 1)
node_mma_kernel(const float* __restrict__ h,
                const float* __restrict__ Wn1, const float* __restrict__ bn1,
                const float* __restrict__ Wn2, const float* __restrict__ bn2,
                float* __restrict__ out) {
    extern __shared__ uint32_t smu[];
    uint32_t* As32 = smu;
    uint32_t* Bs32 = As32 + 27136;

    const int tid = threadIdx.x;
    const int w = tid >> 5, lane = tid & 31;
    const int g = lane >> 2, t = lane & 3;
    const int rw0 = (w & 3) * 32, cn0 = (w >> 2) * 64;
    const int n0 = blockIdx.x * 128;

    {
        int r = tid >> 1, part = tid & 1;
        int n = n0 + r;
        int nc = (n < NN) ? n : (NN - 1);
        uint32_t* dst = As32 + r * NLKA;
        if (part == 0) {
            const float4* hp = (const float4*)(h + (size_t)nc * 64);
#pragma unroll
            for (int q = 0; q < 16; q++) {
                float4 f = hp[q];
                dst[q * 4 + 0] = rna_tf32(f.x); dst[q * 4 + 1] = rna_tf32(f.y);
                dst[q * 4 + 2] = rna_tf32(f.z); dst[q * 4 + 3] = rna_tf32(f.w);
            }
            const float4* ap = (const float4*)(g_aggr + (size_t)nc * 128);
#pragma unroll
            for (int q = 0; q < 8; q++) {
                float4 f = ap[q];
                dst[64 + q * 4 + 0] = rna_tf32(f.x); dst[64 + q * 4 + 1] = rna_tf32(f.y);
                dst[64 + q * 4 + 2] = rna_tf32(f.z); dst[64 + q * 4 + 3] = rna_tf32(f.w);
            }
        } else {
            const float4* ap = (const float4*)(g_aggr + (size_t)nc * 128 + 32);
#pragma unroll
            for (int q = 0; q < 24; q++) {
                float4 f = ap[q];
                dst[96 + q * 4 + 0] = rna_tf32(f.x); dst[96 + q * 4 + 1] = rna_tf32(f.y);
                dst[96 + q * 4 + 2] = rna_tf32(f.z); dst[96 + q * 4 + 3] = rna_tf32(f.w);
            }
        }
    }
    for (int idx = tid; idx < 192 * 32; idx += 256) {
        int k = idx >> 5, j = idx & 31;
        float4 f = ((const float4*)Wn1)[k * 32 + j];
        uint32_t* d = Bs32 + k * NLKB + j * 4;
        d[0] = rna_tf32(f.x); d[1] = rna_tf32(f.y); d[2] = rna_tf32(f.z); d[3] = rna_tf32(f.w);
    }
    __syncthreads();

    float c[2][8][4];
#pragma unroll
    for (int nt = 0; nt < 8; nt++) {
        float b0v = bn1[cn0 + nt * 8 + 2 * t];
        float b1v = bn1[cn0 + nt * 8 + 2 * t + 1];
        c[0][nt][0] = b0v; c[0][nt][1] = b1v; c[0][nt][2] = b0v; c[0][nt][3] = b1v;
        c[1][nt][0] = b0v; c[1][nt][1] = b1v; c[1][nt][2] = b0v; c[1][nt][3] = b1v;
    }
    {
        const uint32_t* ar0 = As32 + (rw0 + g) * NLKA + t;
        const uint32_t* ar1 = As32 + (rw0 + 16 + g) * NLKA + t;
        const uint32_t* br  = Bs32 + t * NLKB + cn0 + g;
#pragma unroll 1
        for (int kb = 0; kb < 24; kb++) {
            uint32_t a0[4], a1[4];
            a0[0] = ar0[kb * 8];       a0[1] = ar0[8 * NLKA + kb * 8];
            a0[2] = ar0[kb * 8 + 4];   a0[3] = ar0[8 * NLKA + kb * 8 + 4];
            a1[0] = ar1[kb * 8];       a1[1] = ar1[8 * NLKA + kb * 8];
            a1[2] = ar1[kb * 8 + 4];   a1[3] = ar1[8 * NLKA + kb * 8 + 4];
#pragma unroll
            for (int nt = 0; nt < 8; nt++) {
                uint32_t b0 = br[(kb * 8) * NLKB + nt * 8];
                uint32_t b1 = br[(kb * 8 + 4) * NLKB + nt * 8];
                mma8(c[0][nt], a0, b0, b1);
                mma8(c[1][nt], a1, b0, b1);
            }
        }
    }
    __syncthreads();
#pragma unroll
    for (int mh = 0; mh < 2; mh++) {
        int r0 = rw0 + mh * 16 + g;
#pragma unroll
        for (int nt = 0; nt < 8; nt++) {
            int col = cn0 + nt * 8 + 2 * t;
            As32[r0 * NLKA + col]           = rna_tf32(silu_t(c[mh][nt][0]));
            As32[r0 * NLKA + col + 1]       = rna_tf32(silu_t(c[mh][nt][1]));
            As32[(r0 + 8) * NLKA + col]     = rna_tf32(silu_t(c[mh][nt][2]));
            As32[(r0 + 8) * NLKA + col + 1] = rna_tf32(silu_t(c[mh][nt][3]));
        }
    }
    for (int idx = tid; idx < 128 * 16; idx += 256) {
        int k = idx >> 4, j = idx & 15;
        float4 f = ((const float4*)Wn2)[k * 16 + j];
        uint32_t* d = Bs32 + k * NLKB + j * 4;
        d[0] = rna_tf32(f.x); d[1] = rna_tf32(f.y); d[2] = rna_tf32(f.z); d[3] = rna_tf32(f.w);
    }
    __syncthreads();

    {
        const int rz = w * 16;
        float c2[8][4];
#pragma unroll
        for (int nt = 0; nt < 8; nt++) {
            float b0v = bn2[nt * 8 + 2 * t];
            float b1v = bn2[nt * 8 + 2 * t + 1];
            c2[nt][0] = b0v; c2[nt][1] = b1v; c2[nt][2] = b0v; c2[nt][3] = b1v;
        }
        const uint32_t* ar = As32 + (rz + g) * NLKA + t;
        const uint32_t* br = Bs32 + t * NLKB + g;
#pragma unroll 1
        for (int kb = 0; kb < 16; kb++) {
            uint32_t a0[4];
            a0[0] = ar[kb * 8];       a0[1] = ar[8 * NLKA + kb * 8];
            a0[2] = ar[kb * 8 + 4];   a0[3] = ar[8 * NLKA + kb * 8 + 4];
#pragma unroll
            for (int nt = 0; nt < 8; nt++) {
                uint32_t b0 = br[(kb * 8) * NLKB + nt * 8];
                uint32_t b1 = br[(kb * 8 + 4) * NLKB + nt * 8];
                mma8(c2[nt], a0, b0, b1);
            }
        }
        int nA = n0 + rz + g, nB = nA + 8;
#pragma unroll
        for (int nt = 0; nt < 8; nt++) {
            int col = nt * 8 + 2 * t;
            if (nA < NN) {
                float2 hv = *(const float2*)(h + (size_t)nA * 64 + col);
                float2 o; o.x = hv.x + c2[nt][0]; o.y = hv.y + c2[nt][1];
                *(float2*)(out + (size_t)nA * 64 + col) = o;
            }
            if (nB < NN) {
                float2 hv = *(const float2*)(h + (size_t)nB * 64 + col);
                float2 o; o.x = hv.x + c2[nt][2]; o.y = hv.y + c2[nt][3];
                *(float2*)(out + (size_t)nB * 64 + col) = o;
            }
        }
    }
}

// ---------------- launch ----------------
extern "C" void kernel_launch(void* const* d_in, const int* in_sizes, int n_in,
                              void* d_out, int out_size) {
    const float* h   = (const float*)d_in[0];
    const float* x   = (const float*)d_in[1];
    const float* v   = (const float*)d_in[2];
    const int*   ei  = (const int*)d_in[3];
    const float* ea  = (const float*)d_in[4];
    const float* Wm1 = (const float*)d_in[5];
    const float* bm1 = (const float*)d_in[6];
    const float* Wm2 = (const float*)d_in[7];
    const float* bm2 = (const float*)d_in[8];
    const float* Wn1 = (const float*)d_in[9];
    const float* bn1 = (const float*)d_in[10];
    const float* Wn2 = (const float*)d_in[11];
    const float* bn2 = (const float*)d_in[12];
    const float* Wc1 = (const float*)d_in[13];
    const float* bc1 = (const float*)d_in[14];
    const float* Wc2 = (const float*)d_in[15];
    const float* bc2 = (const float*)d_in[16];
    const float* Wv1 = (const float*)d_in[17];
    const float* bv1 = (const float*)d_in[18];
    const float* Wv2 = (const float*)d_in[19];
    const float* bv2 = (const float*)d_in[20];
    float* out = (float*)d_out;

    cudaFuncSetAttribute(edge_mma_kernel, cudaFuncAttributeMaxDynamicSharedMemorySize, EDGE_SMEM_BYTES);
    cudaFuncSetAttribute(node_mma_kernel, cudaFuncAttributeMaxDynamicSharedMemorySize, NODE_SMEM_BYTES);

    setup_kernel<<<2048, 256>>>(x, v, out, Wm1, Wm2, Wc1, Wv1);
    edge_mma_kernel<<<EE / 128, 256, EDGE_SMEM_BYTES>>>(
        h, x, ei, ea, bm1, bm2, bc1, bc2, bv1, bv2, Wc2, Wv2,
        out + (size_t)NN * 64, out + (size_t)NN * 64 + (size_t)NN * 3);
    node_mma_kernel<<<(NN + 127) / 128, 256, NODE_SMEM_BYTES>>>(h, Wn1, bn1, Wn2, bn2, out);
}